// round 14
// baseline (speedup 1.0000x reference)
#include <cuda_runtime.h>
#include <cuda_fp16.h>
#include <math.h>
#include <stdint.h>

#define B_ 32
#define C_ 256
#define L_ 4096
#define H_ (2*C_)
#define BL_ (B_*L_)

// ---------------- scratch (device globals; no allocation allowed) ----------
__device__ uint16_t g_xt[(size_t)B_*L_*C_];   // x transposed [B,L,C], fp16
__device__ uint16_t g_y1[(size_t)B_*L_*C_];   // conv1 out [B,L,C], fp16
__device__ uint16_t g_xp[(size_t)B_*L_*C_];   // conv2 out [B,L,C], fp16
__device__ uint16_t g_t1[(size_t)B_*L_*C_];   // sd / fw, fp16
__device__ uint16_t g_h [(size_t)B_*L_*H_];   // hidden [BL,2C], fp16
__device__ uint16_t g_dct [C_*C_];            // [N=256][K=256] fp16
__device__ uint16_t g_fc1r[H_*C_];            // [N=2C][K=C] fp16 (native)
__device__ uint16_t g_fc2r[C_*H_];            // [N=C][K=2C] fp16 (native)
__device__ uint16_t g_w1r[C_*3*C_];           // [co][k*C+ci] fp16
__device__ uint16_t g_w2r[C_*3*C_];           // [co][k*C+ci] fp16
__device__ float g_bn1s[C_], g_bn1t[C_], g_bn2s[C_], g_bn2t[C_];

// ---------------- helpers ---------------------------------------------------
__device__ __forceinline__ uint32_t smem_u32(const void* p) {
    return (uint32_t)__cvta_generic_to_shared(p);
}
__device__ __forceinline__ void cp16p(uint32_t dst, const void* src, uint32_t sz) {
    asm volatile("cp.async.cg.shared.global [%0], [%1], 16, %2;"
                 :: "r"(dst), "l"(src), "r"(sz));
}
#define CP_COMMIT() asm volatile("cp.async.commit_group;")
#define CP_WAIT0()  asm volatile("cp.async.wait_group 0;" ::: "memory")
#define CP_WAIT1()  asm volatile("cp.async.wait_group 1;" ::: "memory")

__device__ __forceinline__ void mma_f16(float c[4],
        uint32_t a0, uint32_t a1, uint32_t a2, uint32_t a3,
        uint32_t b0, uint32_t b1) {
    asm volatile(
        "mma.sync.aligned.m16n8k16.row.col.f32.f16.f16.f32 "
        "{%0,%1,%2,%3}, {%4,%5,%6,%7}, {%8,%9}, {%0,%1,%2,%3};"
        : "+f"(c[0]), "+f"(c[1]), "+f"(c[2]), "+f"(c[3])
        : "r"(a0), "r"(a1), "r"(a2), "r"(a3), "r"(b0), "r"(b1));
}
__device__ __forceinline__ void ldsm4(uint32_t& r0, uint32_t& r1,
                                      uint32_t& r2, uint32_t& r3, uint32_t addr) {
    asm volatile("ldmatrix.sync.aligned.m8n8.x4.shared.b16 {%0,%1,%2,%3}, [%4];"
                 : "=r"(r0), "=r"(r1), "=r"(r2), "=r"(r3) : "r"(addr));
}

// ---------------- precompute: all weights (fp16) + BN affines ---------------
__global__ void precompute_kernel(const float* __restrict__ fc1_w,
                                  const float* __restrict__ fc2_w,
                                  const float* __restrict__ w1,
                                  const float* __restrict__ w2,
                                  const float* __restrict__ bn1_g, const float* __restrict__ bn1_b,
                                  const float* __restrict__ bn1_m, const float* __restrict__ bn1_v,
                                  const float* __restrict__ bn2_g, const float* __restrict__ bn2_b,
                                  const float* __restrict__ bn2_m, const float* __restrict__ bn2_v) {
    int idx = blockIdx.x * blockDim.x + threadIdx.x;
    if (idx < C_) {
        float s1 = bn1_g[idx] * rsqrtf(bn1_v[idx] + 1e-5f);
        g_bn1s[idx] = s1; g_bn1t[idx] = bn1_b[idx] - bn1_m[idx]*s1;
        float s2 = bn2_g[idx] * rsqrtf(bn2_v[idx] + 1e-5f);
        g_bn2s[idx] = s2; g_bn2t[idx] = bn2_b[idx] - bn2_m[idx]*s2;
    }
    if (idx < C_*C_) {
        int k = idx / C_, n = idx % C_;
        double v = 2.0 * cos(M_PI * (double)k * (2.0*n + 1.0) / (2.0 * C_));
        g_dct[idx] = __half_as_ushort(__float2half_rn((float)v));
    }
    if (idx < C_*H_) {
        g_fc1r[idx] = __half_as_ushort(__float2half_rn(fc1_w[idx]));
        g_fc2r[idx] = __half_as_ushort(__float2half_rn(fc2_w[idx]));
    }
    if (idx < 3*C_*C_) {
        int co = idx / (3*C_);
        int rem = idx % (3*C_);
        int k = rem / C_, ci = rem % C_;
        g_w1r[idx] = __half_as_ushort(__float2half_rn(w1[(size_t)co*3*C_ + ci*3 + k]));
        g_w2r[idx] = __half_as_ushort(__float2half_rn(w2[(size_t)co*3*C_ + ci*3 + k]));
    }
}

// -------- transpose+round: xt[b][l][c] = fp16(x[b][c][l]) -------------------
__global__ void transpose_round_kernel(const float* __restrict__ x, __half* __restrict__ xt) {
    __shared__ float tile[32][65];
    int b = blockIdx.z, c0 = blockIdx.x*32, l0 = blockIdx.y*64;
    int tid = threadIdx.x;                 // 256
    #pragma unroll
    for (int i = 0; i < 2; i++) {
        int id = tid + i*256;
        int r = id >> 4, q = id & 15;
        float4 v = *(const float4*)&x[((size_t)b*C_ + c0 + r)*L_ + l0 + q*4];
        tile[r][q*4+0] = v.x; tile[r][q*4+1] = v.y;
        tile[r][q*4+2] = v.z; tile[r][q*4+3] = v.w;
    }
    __syncthreads();
    int r = tid >> 2;
    int q = tid & 3;
    __half hbuf[8];
    #pragma unroll
    for (int j = 0; j < 8; j++)
        hbuf[j] = __float2half_rn(tile[q*8 + j][r]);
    *(uint4*)&xt[((size_t)b*L_ + l0 + r)*C_ + c0 + q*8] = *(uint4*)hbuf;
}

// ===== fp16 tensor-core GEMM (proven): CTA 128x128, 8 warps, 2-stage =======
#define TILEB (128*144)              // 18432 B per operand per stage
#define GH_SMEM (4*TILEB)            // 73728

__global__ void __launch_bounds__(256, 2)
gemmh(const __half* __restrict__ A, const __half* __restrict__ Bw,
      __half* __restrict__ D, int N, int K, int conv_mode,
      const float* __restrict__ e1, const float* __restrict__ e2, int epi) {
    extern __shared__ unsigned char sm[];
    const uint32_t sbase = smem_u32(sm);

    int tid = threadIdx.x, lane = tid & 31, wid = tid >> 5;
    int wm = (wid & 1) * 64, wn = (wid >> 1) * 32;
    int g = lane >> 2, tg = lane & 3;
    int lr = lane & 7, sel = lane >> 3;
    size_t n0 = (size_t)blockIdx.x * 128;
    size_t m0 = (size_t)blockIdx.y * 128;
    int bidx = (int)(m0 >> 12);
    int l0   = (int)(m0 & (L_ - 1));

    float acc[4][4][4] = {};
    int ntls = K >> 6;

    auto load_tile = [&](int t, int buf) {
        uint32_t ab = sbase + (uint32_t)buf * TILEB;
        uint32_t bb = sbase + 2u * TILEB + (uint32_t)buf * TILEB;
        #pragma unroll
        for (int i = 0; i < 4; i++) {
            int ch = tid + i * 256;
            int r = ch >> 3, c16 = ch & 7;
            uint32_t doff = r * 144 + c16 * 16;
            if (conv_mode) {
                int tap = t >> 2;
                int ci0 = (t & 3) * 64 + c16 * 8;
                int sl = l0 + r + tap - 1;
                uint32_t sz = ((unsigned)sl < (unsigned)L_) ? 16u : 0u;
                int slc = sl < 0 ? 0 : (sl >= L_ ? L_ - 1 : sl);
                cp16p(ab + doff, &A[((size_t)bidx * L_ + slc) * C_ + ci0], sz);
            } else {
                cp16p(ab + doff, &A[(m0 + r) * (size_t)K + t * 64 + c16 * 8], 16);
            }
            cp16p(bb + doff, &Bw[(n0 + r) * (size_t)K + t * 64 + c16 * 8], 16);
        }
    };

    load_tile(0, 0); CP_COMMIT();
    if (ntls > 1) { load_tile(1, 1); CP_COMMIT(); }

    for (int t = 0; t < ntls; t++) {
        if (t + 1 < ntls) CP_WAIT1(); else CP_WAIT0();
        __syncthreads();
        int buf = t & 1;
        uint32_t ab = sbase + (uint32_t)buf * TILEB;
        uint32_t bb = sbase + 2u * TILEB + (uint32_t)buf * TILEB;
        #pragma unroll
        for (int ks = 0; ks < 4; ks++) {
            int kb = ks * 16;
            uint32_t af[4][4], bf[4][2];
            #pragma unroll
            for (int mt = 0; mt < 4; mt++) {
                uint32_t a = ab + (uint32_t)(wm + mt*16 + (sel & 1)*8 + lr) * 144
                                + (uint32_t)(kb + (sel >> 1)*8) * 2;
                ldsm4(af[mt][0], af[mt][1], af[mt][2], af[mt][3], a);
            }
            #pragma unroll
            for (int q = 0; q < 2; q++) {
                uint32_t a = bb + (uint32_t)(wn + q*16 + (sel >> 1)*8 + lr) * 144
                                + (uint32_t)(kb + (sel & 1)*8) * 2;
                ldsm4(bf[q*2][0], bf[q*2][1], bf[q*2+1][0], bf[q*2+1][1], a);
            }
            #pragma unroll
            for (int mt = 0; mt < 4; mt++)
                #pragma unroll
                for (int nt = 0; nt < 4; nt++)
                    mma_f16(acc[mt][nt], af[mt][0], af[mt][1], af[mt][2], af[mt][3],
                            bf[nt][0], bf[nt][1]);
        }
        __syncthreads();
        if (t + 2 < ntls) { load_tile(t + 2, buf); CP_COMMIT(); }
    }

    #pragma unroll
    for (int mt = 0; mt < 4; mt++)
        #pragma unroll
        for (int nt = 0; nt < 4; nt++)
            #pragma unroll
            for (int h = 0; h < 2; h++) {
                size_t row = m0 + wm + mt*16 + g + h*8;
                int col = (int)n0 + wn + nt*8 + tg*2;
                float v0 = acc[mt][nt][h*2+0], v1 = acc[mt][nt][h*2+1];
                if (epi == 1) { v0 = fmaxf(v0, 0.f); v1 = fmaxf(v1, 0.f); }
                else if (epi == 2) { v0 = 1.f/(1.f+expf(-v0)); v1 = 1.f/(1.f+expf(-v1)); }
                else if (epi >= 3) {
                    v0 = v0 * e1[col]   + e2[col];
                    v1 = v1 * e1[col+1] + e2[col+1];
                    if (epi == 4) { v0 = fmaxf(v0, 0.f); v1 = fmaxf(v1, 0.f); }
                }
                *(__half2*)&D[row * (size_t)N + col] = __floats2half2_rn(v0, v1);
            }
}

// ===== DCT GEMM + fused LN1: sd = LN(xp @ Dm^T), one CTA owns full N=256 ===
// Two sequential n-halves; half 0 stashed fp16 in smem, half 1 in regs.
// Two-pass LN stats via smem atomics; writes sd directly to D.
#define DST_STR 136
#define DCT_STASH_OFF (4*TILEB)                            // 73728
#define DCT_SUM_OFF   (DCT_STASH_OFF + 128*DST_STR*2)      // 108544
#define DCT_SQ_OFF    (DCT_SUM_OFF + 512)
#define DCT_G_OFF     (DCT_SQ_OFF + 512)
#define DCT_B_OFF     (DCT_G_OFF + 1024)
#define DCT_SMEM      (DCT_B_OFF + 1024)                   // 111616

__global__ void __launch_bounds__(256, 2)
dct_ln_kernel(const __half* __restrict__ A, const __half* __restrict__ Bw,
              __half* __restrict__ D,
              const float* __restrict__ gw, const float* __restrict__ bw) {
    extern __shared__ unsigned char sm[];
    const uint32_t sbase = smem_u32(sm);
    float* ssum = (float*)(sm + DCT_SUM_OFF);
    float* ssq  = (float*)(sm + DCT_SQ_OFF);
    float* gbuf = (float*)(sm + DCT_G_OFF);
    float* bbuf = (float*)(sm + DCT_B_OFF);
    __half* stash = (__half*)(sm + DCT_STASH_OFF);

    int tid = threadIdx.x, lane = tid & 31, wid = tid >> 5;
    int wm = (wid & 1) * 64, wn = (wid >> 1) * 32;
    int g = lane >> 2, tg = lane & 3;
    int lr = lane & 7, sel = lane >> 3;
    size_t m0 = (size_t)blockIdx.x * 128;

    gbuf[tid] = gw[tid];
    bbuf[tid] = bw[tid];
    if (tid < 128) { ssum[tid] = 0.f; ssq[tid] = 0.f; }

    __half2 rh[4][4][2];   // rounded fragments of current half

    #pragma unroll 1
    for (int nx = 0; nx < 2; nx++) {
        size_t n0 = (size_t)nx * 128;
        float acc[4][4][4] = {};

        auto load_tile = [&](int t, int buf) {
            uint32_t ab = sbase + (uint32_t)buf * TILEB;
            uint32_t bb = sbase + 2u * TILEB + (uint32_t)buf * TILEB;
            #pragma unroll
            for (int i = 0; i < 4; i++) {
                int ch = tid + i * 256;
                int r = ch >> 3, c16 = ch & 7;
                uint32_t doff = r * 144 + c16 * 16;
                cp16p(ab + doff, &A[(m0 + r) * (size_t)C_ + t * 64 + c16 * 8], 16);
                cp16p(bb + doff, &Bw[(n0 + r) * (size_t)C_ + t * 64 + c16 * 8], 16);
            }
        };

        load_tile(0, 0); CP_COMMIT();
        load_tile(1, 1); CP_COMMIT();
        for (int t = 0; t < 4; t++) {
            if (t + 1 < 4) CP_WAIT1(); else CP_WAIT0();
            __syncthreads();
            int buf = t & 1;
            uint32_t ab = sbase + (uint32_t)buf * TILEB;
            uint32_t bb = sbase + 2u * TILEB + (uint32_t)buf * TILEB;
            #pragma unroll
            for (int ks = 0; ks < 4; ks++) {
                int kb = ks * 16;
                uint32_t af[4][4], bf[4][2];
                #pragma unroll
                for (int mt = 0; mt < 4; mt++) {
                    uint32_t a = ab + (uint32_t)(wm + mt*16 + (sel & 1)*8 + lr) * 144
                                    + (uint32_t)(kb + (sel >> 1)*8) * 2;
                    ldsm4(af[mt][0], af[mt][1], af[mt][2], af[mt][3], a);
                }
                #pragma unroll
                for (int q = 0; q < 2; q++) {
                    uint32_t a = bb + (uint32_t)(wn + q*16 + (sel >> 1)*8 + lr) * 144
                                    + (uint32_t)(kb + (sel & 1)*8) * 2;
                    ldsm4(bf[q*2][0], bf[q*2][1], bf[q*2+1][0], bf[q*2+1][1], a);
                }
                #pragma unroll
                for (int mt = 0; mt < 4; mt++)
                    #pragma unroll
                    for (int nt = 0; nt < 4; nt++)
                        mma_f16(acc[mt][nt], af[mt][0], af[mt][1], af[mt][2], af[mt][3],
                                bf[nt][0], bf[nt][1]);
            }
            __syncthreads();
            if (t + 2 < 4) { load_tile(t + 2, buf); CP_COMMIT(); }
        }

        // round to fp16 fragments
        #pragma unroll
        for (int mt = 0; mt < 4; mt++)
            #pragma unroll
            for (int nt = 0; nt < 4; nt++)
                #pragma unroll
                for (int h = 0; h < 2; h++)
                    rh[mt][nt][h] = __floats2half2_rn(acc[mt][nt][h*2+0], acc[mt][nt][h*2+1]);

        if (nx == 0) {
            // stash half 0 (bank pattern (4g+tg) mod 32 - conflict free)
            #pragma unroll
            for (int mt = 0; mt < 4; mt++)
                #pragma unroll
                for (int h = 0; h < 2; h++) {
                    int row = wm + mt*16 + g + h*8;
                    #pragma unroll
                    for (int nt = 0; nt < 4; nt++)
                        *(__half2*)&stash[row*DST_STR + wn + nt*8 + tg*2] = rh[mt][nt][h];
                }
        }
    }
    __syncthreads();   // stash + zeroed stats visible; mainloop done

    // ---- pass 1: row sums (fp16-rounded values, both halves) --------------
    #pragma unroll
    for (int mt = 0; mt < 4; mt++)
        #pragma unroll
        for (int h = 0; h < 2; h++) {
            int row = wm + mt*16 + g + h*8;
            float p = 0.f;
            #pragma unroll
            for (int nt = 0; nt < 4; nt++) {
                float2 f = __half22float2(rh[mt][nt][h]);
                p += f.x + f.y;
            }
            atomicAdd(&ssum[row], p);
        }
    {
        int srow = tid >> 1, cb = (tid & 1) * 64;
        float p = 0.f;
        #pragma unroll
        for (int j = 0; j < 8; j++) {
            uint4 u = *(uint4*)&stash[srow*DST_STR + cb + j*8];
            __half2 hp[4]; *(uint4*)hp = u;
            #pragma unroll
            for (int q = 0; q < 4; q++) {
                float2 f = __half22float2(hp[q]);
                p += f.x + f.y;
            }
        }
        atomicAdd(&ssum[srow], p);
    }
    __syncthreads();

    // ---- pass 2: row sum of squared deviations -----------------------------
    #pragma unroll
    for (int mt = 0; mt < 4; mt++)
        #pragma unroll
        for (int h = 0; h < 2; h++) {
            int row = wm + mt*16 + g + h*8;
            float mean = ssum[row] * (1.f / C_);
            float p = 0.f;
            #pragma unroll
            for (int nt = 0; nt < 4; nt++) {
                float2 f = __half22float2(rh[mt][nt][h]);
                float d0 = f.x - mean, d1 = f.y - mean;
                p += d0*d0 + d1*d1;
            }
            atomicAdd(&ssq[row], p);
        }
    {
        int srow = tid >> 1, cb = (tid & 1) * 64;
        float mean = ssum[srow] * (1.f / C_);
        float p = 0.f;
        #pragma unroll
        for (int j = 0; j < 8; j++) {
            uint4 u = *(uint4*)&stash[srow*DST_STR + cb + j*8];
            __half2 hp[4]; *(uint4*)hp = u;
            #pragma unroll
            for (int q = 0; q < 4; q++) {
                float2 f = __half22float2(hp[q]);
                float d0 = f.x - mean, d1 = f.y - mean;
                p += d0*d0 + d1*d1;
            }
        }
        atomicAdd(&ssq[srow], p);
    }
    __syncthreads();

    // ---- normalize + write --------------------------------------------------
    // half 1 (cols 128-255) from regs
    #pragma unroll
    for (int mt = 0; mt < 4; mt++)
        #pragma unroll
        for (int h = 0; h < 2; h++) {
            int row = wm + mt*16 + g + h*8;
            float mean = ssum[row] * (1.f / C_);
            float inv = rsqrtf(ssq[row] * (1.f / C_) + 1e-6f);
            #pragma unroll
            for (int nt = 0; nt < 4; nt++) {
                int col = 128 + wn + nt*8 + tg*2;
                float2 f = __half22float2(rh[mt][nt][h]);
                float y0 = (f.x - mean)*inv*gbuf[col]   + bbuf[col];
                float y1 = (f.y - mean)*inv*gbuf[col+1] + bbuf[col+1];
                *(__half2*)&D[(m0 + row)*C_ + col] = __floats2half2_rn(y0, y1);
            }
        }
    // half 0 (cols 0-127) from stash; thread -> row=tid>>1, 64 cols
    {
        int srow = tid >> 1, cb = (tid & 1) * 64;
        float mean = ssum[srow] * (1.f / C_);
        float inv = rsqrtf(ssq[srow] * (1.f / C_) + 1e-6f);
        #pragma unroll
        for (int j = 0; j < 8; j++) {
            uint4 u = *(uint4*)&stash[srow*DST_STR + cb + j*8];
            __half2 hp[4]; *(uint4*)hp = u;
            __half2 o[4];
            #pragma unroll
            for (int q = 0; q < 4; q++) {
                int col = cb + j*8 + q*2;
                float2 f = __half22float2(hp[q]);
                float y0 = (f.x - mean)*inv*gbuf[col]   + bbuf[col];
                float y1 = (f.y - mean)*inv*gbuf[col+1] + bbuf[col+1];
                o[q] = __floats2half2_rn(y0, y1);
            }
            *(uint4*)&D[(m0 + srow)*C_ + cb + j*8] = *(uint4*)o;
        }
    }
}

// ==== fused LN2 + final: out[b,c,l] = relu(xp[b,l,c]*LN(fw)[b,l,c] + x) ====
__global__ void ln_final_kernel(const __half* __restrict__ t1, const __half* __restrict__ xp,
                                const float* __restrict__ x,
                                const float* __restrict__ gw, const float* __restrict__ bw,
                                float* __restrict__ out) {
    __shared__ float tile[32][257];
    int tid = threadIdx.x, lane = tid & 31, warp = tid >> 5;
    int b = blockIdx.y, l0 = blockIdx.x * 32;

    const float4* g4 = (const float4*)gw;
    const float4* b4 = (const float4*)bw;
    float4 ga = g4[lane*2], gb = g4[lane*2+1], ba = b4[lane*2], bb = b4[lane*2+1];
    float gv[8] = {ga.x, ga.y, ga.z, ga.w, gb.x, gb.y, gb.z, gb.w};
    float bv[8] = {ba.x, ba.y, ba.z, ba.w, bb.x, bb.y, bb.z, bb.w};

    #pragma unroll
    for (int r = 0; r < 4; r++) {
        int rt = r * 8 + warp;
        size_t row = (size_t)b * L_ + l0 + rt;
        uint4 raw = ((const uint4*)(t1 + row * C_))[lane];
        __half2 hp[4]; *(uint4*)hp = raw;
        float v[8];
        #pragma unroll
        for (int q = 0; q < 4; q++) {
            float2 f = __half22float2(hp[q]);
            v[q*2] = f.x; v[q*2+1] = f.y;
        }
        float s = 0.f;
        #pragma unroll
        for (int j = 0; j < 8; j++) s += v[j];
        #pragma unroll
        for (int o = 16; o; o >>= 1) s += __shfl_xor_sync(0xffffffffu, s, o);
        float mean = s * (1.f / C_);
        float s2 = 0.f;
        #pragma unroll
        for (int j = 0; j < 8; j++) { v[j] -= mean; s2 += v[j]*v[j]; }
        #pragma unroll
        for (int o = 16; o; o >>= 1) s2 += __shfl_xor_sync(0xffffffffu, s2, o);
        float inv = rsqrtf(s2 * (1.f / C_) + 1e-6f);

        uint4 xraw = ((const uint4*)(xp + row * C_))[lane];
        __half2 xh[4]; *(uint4*)xh = xraw;
        #pragma unroll
        for (int q = 0; q < 4; q++) {
            float2 xf = __half22float2(xh[q]);
            float fw0 = v[q*2]   * inv * gv[q*2]   + bv[q*2];
            float fw1 = v[q*2+1] * inv * gv[q*2+1] + bv[q*2+1];
            tile[rt][lane*8 + q*2]     = xf.x * fw0;
            tile[rt][lane*8 + q*2 + 1] = xf.y * fw1;
        }
    }
    __syncthreads();

    int l4 = (tid & 7) * 4;
    int cb = tid >> 3;
    #pragma unroll
    for (int j = 0; j < 8; j++) {
        int c = cb + j * 32;
        size_t gi = ((size_t)b * C_ + c) * L_ + l0 + l4;
        float4 xv = *(const float4*)&x[gi];
        float4 o;
        o.x = fmaxf(tile[l4+0][c] + xv.x, 0.f);
        o.y = fmaxf(tile[l4+1][c] + xv.y, 0.f);
        o.z = fmaxf(tile[l4+2][c] + xv.z, 0.f);
        o.w = fmaxf(tile[l4+3][c] + xv.w, 0.f);
        *(float4*)&out[gi] = o;
    }
}

// ---------------------------------------------------------------------------
extern "C" void kernel_launch(void* const* d_in, const int* in_sizes, int n_in,
                              void* d_out, int out_size) {
    const float* x       = (const float*)d_in[0];
    const float* conv1_w = (const float*)d_in[1];
    const float* bn1_g   = (const float*)d_in[2];
    const float* bn1_b   = (const float*)d_in[3];
    const float* bn1_m   = (const float*)d_in[4];
    const float* bn1_v   = (const float*)d_in[5];
    const float* conv2_w = (const float*)d_in[6];
    const float* bn2_g   = (const float*)d_in[7];
    const float* bn2_b   = (const float*)d_in[8];
    const float* bn2_m   = (const float*)d_in[9];
    const float* bn2_v   = (const float*)d_in[10];
    const float* fc1_w   = (const float*)d_in[11];
    const float* fc2_w   = (const float*)d_in[12];
    const float* ln_g    = (const float*)d_in[13];
    const float* ln_b    = (const float*)d_in[14];
    float* out = (float*)d_out;

    void *xt, *y1, *xp, *t1, *h, *dct, *fc1r, *fc2r, *w1r, *w2r;
    void *bn1s, *bn1t, *bn2s, *bn2t;
    cudaGetSymbolAddress(&xt,   g_xt);
    cudaGetSymbolAddress(&y1,   g_y1);
    cudaGetSymbolAddress(&xp,   g_xp);
    cudaGetSymbolAddress(&t1,   g_t1);
    cudaGetSymbolAddress(&h,    g_h);
    cudaGetSymbolAddress(&dct,  g_dct);
    cudaGetSymbolAddress(&fc1r, g_fc1r);
    cudaGetSymbolAddress(&fc2r, g_fc2r);
    cudaGetSymbolAddress(&w1r,  g_w1r);
    cudaGetSymbolAddress(&w2r,  g_w2r);
    cudaGetSymbolAddress(&bn1s, g_bn1s);
    cudaGetSymbolAddress(&bn1t, g_bn1t);
    cudaGetSymbolAddress(&bn2s, g_bn2s);
    cudaGetSymbolAddress(&bn2t, g_bn2t);

    cudaFuncSetAttribute(gemmh, cudaFuncAttributeMaxDynamicSharedMemorySize, GH_SMEM);
    cudaFuncSetAttribute(dct_ln_kernel, cudaFuncAttributeMaxDynamicSharedMemorySize, DCT_SMEM);

    // 0. precompute fp16 weights + transpose/round x
    precompute_kernel<<<(3*C_*C_ + 255)/256, 256>>>(
        fc1_w, fc2_w, conv1_w, conv2_w,
        bn1_g, bn1_b, bn1_m, bn1_v, bn2_g, bn2_b, bn2_m, bn2_v);
    {
        dim3 grid(C_/32, L_/64, B_);
        transpose_round_kernel<<<grid, 256>>>(x, (__half*)xt);
    }

    // 1. conv1+bn1+relu -> y1 [B,L,C]
    gemmh<<<dim3(C_/128, BL_/128), 256, GH_SMEM>>>(
        (const __half*)xt, (const __half*)w1r, (__half*)y1, C_, 3*C_, 1,
        (const float*)bn1s, (const float*)bn1t, 4);
    // 2. conv2+bn2 -> xp [B,L,C]
    gemmh<<<dim3(C_/128, BL_/128), 256, GH_SMEM>>>(
        (const __half*)y1, (const __half*)w2r, (__half*)xp, C_, 3*C_, 1,
        (const float*)bn2s, (const float*)bn2t, 3);
    // 3+4. sd = LN(xp @ Dm^T) -> t1  (fused DCT GEMM + LN1)
    dct_ln_kernel<<<BL_/128, 256, DCT_SMEM>>>(
        (const __half*)xp, (const __half*)dct, (__half*)t1, ln_g, ln_b);
    // 5. h = relu(sd @ fc1^T)
    gemmh<<<dim3(H_/128, BL_/128), 256, GH_SMEM>>>(
        (const __half*)t1, (const __half*)fc1r, (__half*)h, H_, C_, 0,
        nullptr, nullptr, 1);
    // 6. fw = sigmoid(h @ fc2^T) -> t1
    gemmh<<<dim3(C_/128, BL_/128), 256, GH_SMEM>>>(
        (const __half*)h, (const __half*)fc2r, (__half*)t1, C_, H_, 0,
        nullptr, nullptr, 2);
    // 7+8. fused: fw = LN(t1); out = relu(transpose(xp*fw) + x)
    {
        dim3 grid(L_/32, B_);
        ln_final_kernel<<<grid, 256>>>((const __half*)t1, (const __half*)xp, x,
                                       ln_g, ln_b, out);
    }
}

// round 15
// speedup vs baseline: 1.0557x; 1.0557x over previous
#include <cuda_runtime.h>
#include <cuda_fp16.h>
#include <math.h>
#include <stdint.h>

#define B_ 32
#define C_ 256
#define L_ 4096
#define H_ (2*C_)
#define BL_ (B_*L_)

// ---------------- scratch (device globals; no allocation allowed) ----------
__device__ uint16_t g_xt[(size_t)B_*L_*C_];   // x transposed [B,L,C], fp16
__device__ uint16_t g_y1[(size_t)B_*L_*C_];   // conv1 out [B,L,C], fp16
__device__ uint16_t g_xp[(size_t)B_*L_*C_];   // conv2 out [B,L,C], fp16
__device__ uint16_t g_t1[(size_t)B_*L_*C_];   // freq / sd / fw, fp16
__device__ uint16_t g_h [(size_t)B_*L_*H_];   // hidden [BL,2C], fp16
__device__ uint16_t g_dct [C_*C_];            // [N=256][K=256] fp16
__device__ uint16_t g_fc1r[H_*C_];            // [N=2C][K=C] fp16 (native)
__device__ uint16_t g_fc2r[C_*H_];            // [N=C][K=2C] fp16 (native)
__device__ uint16_t g_w1r[C_*3*C_];           // [co][tap*C+ci] fp16
__device__ uint16_t g_w2r[C_*3*C_];           // [co][tap*C+ci] fp16
__device__ float g_bn1s[C_], g_bn1t[C_], g_bn2s[C_], g_bn2t[C_];

// ---------------- helpers ---------------------------------------------------
__device__ __forceinline__ uint32_t smem_u32(const void* p) {
    return (uint32_t)__cvta_generic_to_shared(p);
}
__device__ __forceinline__ void cp16p(uint32_t dst, const void* src, uint32_t sz) {
    asm volatile("cp.async.cg.shared.global [%0], [%1], 16, %2;"
                 :: "r"(dst), "l"(src), "r"(sz));
}
#define CP_COMMIT() asm volatile("cp.async.commit_group;")
#define CP_WAIT0()  asm volatile("cp.async.wait_group 0;" ::: "memory")
#define CP_WAIT1()  asm volatile("cp.async.wait_group 1;" ::: "memory")

__device__ __forceinline__ void mma_f16(float c[4],
        uint32_t a0, uint32_t a1, uint32_t a2, uint32_t a3,
        uint32_t b0, uint32_t b1) {
    asm volatile(
        "mma.sync.aligned.m16n8k16.row.col.f32.f16.f16.f32 "
        "{%0,%1,%2,%3}, {%4,%5,%6,%7}, {%8,%9}, {%0,%1,%2,%3};"
        : "+f"(c[0]), "+f"(c[1]), "+f"(c[2]), "+f"(c[3])
        : "r"(a0), "r"(a1), "r"(a2), "r"(a3), "r"(b0), "r"(b1));
}
__device__ __forceinline__ void ldsm4(uint32_t& r0, uint32_t& r1,
                                      uint32_t& r2, uint32_t& r3, uint32_t addr) {
    asm volatile("ldmatrix.sync.aligned.m8n8.x4.shared.b16 {%0,%1,%2,%3}, [%4];"
                 : "=r"(r0), "=r"(r1), "=r"(r2), "=r"(r3) : "r"(addr));
}

// ---------------- precompute: all weights (fp16) + BN affines ---------------
__global__ void precompute_kernel(const float* __restrict__ fc1_w,
                                  const float* __restrict__ fc2_w,
                                  const float* __restrict__ w1,
                                  const float* __restrict__ w2,
                                  const float* __restrict__ bn1_g, const float* __restrict__ bn1_b,
                                  const float* __restrict__ bn1_m, const float* __restrict__ bn1_v,
                                  const float* __restrict__ bn2_g, const float* __restrict__ bn2_b,
                                  const float* __restrict__ bn2_m, const float* __restrict__ bn2_v) {
    int idx = blockIdx.x * blockDim.x + threadIdx.x;
    if (idx < C_) {
        float s1 = bn1_g[idx] * rsqrtf(bn1_v[idx] + 1e-5f);
        g_bn1s[idx] = s1; g_bn1t[idx] = bn1_b[idx] - bn1_m[idx]*s1;
        float s2 = bn2_g[idx] * rsqrtf(bn2_v[idx] + 1e-5f);
        g_bn2s[idx] = s2; g_bn2t[idx] = bn2_b[idx] - bn2_m[idx]*s2;
    }
    if (idx < C_*C_) {
        int k = idx / C_, n = idx % C_;
        double v = 2.0 * cos(M_PI * (double)k * (2.0*n + 1.0) / (2.0 * C_));
        g_dct[idx] = __half_as_ushort(__float2half_rn((float)v));
    }
    if (idx < C_*H_) {
        g_fc1r[idx] = __half_as_ushort(__float2half_rn(fc1_w[idx]));
        g_fc2r[idx] = __half_as_ushort(__float2half_rn(fc2_w[idx]));
    }
    if (idx < 3*C_*C_) {
        int co = idx / (3*C_);
        int rem = idx % (3*C_);
        int k = rem / C_, ci = rem % C_;
        g_w1r[idx] = __half_as_ushort(__float2half_rn(w1[(size_t)co*3*C_ + ci*3 + k]));
        g_w2r[idx] = __half_as_ushort(__float2half_rn(w2[(size_t)co*3*C_ + ci*3 + k]));
    }
}

// -------- transpose+round (R10): xt[b][l][c] = fp16(x[b][c][l]) -------------
__global__ void transpose_round_kernel(const float* __restrict__ x, __half* __restrict__ xt) {
    __shared__ float tile[32][33];
    int b = blockIdx.z, c0 = blockIdx.x*32, l0 = blockIdx.y*32;
    int tx = threadIdx.x, ty = threadIdx.y;   // 32 x 8
    #pragma unroll
    for (int i = 0; i < 32; i += 8)
        tile[ty+i][tx] = x[((size_t)b*C_ + c0+ty+i)*L_ + l0 + tx];
    __syncthreads();
    #pragma unroll
    for (int i = 0; i < 32; i += 8)
        xt[((size_t)b*L_ + l0+ty+i)*C_ + c0 + tx] = __float2half_rn(tile[tx][ty+i]);
}

// ===== fp16 tensor-core GEMM (R10 proven): CTA 128x128, 8 warps, 2-stage ===
// A flat [M,K] fp16; B [N,K] row-major fp16. K=64/stage.
// epi: 0 none, 1 relu, 2 sigmoid.
#define TILEB (128*144)              // 18432 B per operand per stage
#define GH_SMEM (4*TILEB)            // 73728

__global__ void __launch_bounds__(256, 2)
gemmh(const __half* __restrict__ A, const __half* __restrict__ Bw,
      __half* __restrict__ D, int N, int K, int epi) {
    extern __shared__ unsigned char sm[];
    const uint32_t sbase = smem_u32(sm);

    int tid = threadIdx.x, lane = tid & 31, wid = tid >> 5;
    int wm = (wid & 1) * 64, wn = (wid >> 1) * 32;
    int g = lane >> 2, tg = lane & 3;
    int lr = lane & 7, sel = lane >> 3;
    size_t n0 = (size_t)blockIdx.x * 128;
    size_t m0 = (size_t)blockIdx.y * 128;

    float acc[4][4][4] = {};
    int ntls = K >> 6;

    auto load_tile = [&](int t, int buf) {
        uint32_t ab = sbase + (uint32_t)buf * TILEB;
        uint32_t bb = sbase + 2u * TILEB + (uint32_t)buf * TILEB;
        #pragma unroll
        for (int i = 0; i < 4; i++) {
            int ch = tid + i * 256;
            int r = ch >> 3, c16 = ch & 7;
            uint32_t doff = r * 144 + c16 * 16;
            cp16p(ab + doff, &A[(m0 + r) * (size_t)K + t * 64 + c16 * 8], 16);
            cp16p(bb + doff, &Bw[(n0 + r) * (size_t)K + t * 64 + c16 * 8], 16);
        }
    };

    load_tile(0, 0); CP_COMMIT();
    if (ntls > 1) { load_tile(1, 1); CP_COMMIT(); }

    for (int t = 0; t < ntls; t++) {
        if (t + 1 < ntls) CP_WAIT1(); else CP_WAIT0();
        __syncthreads();
        int buf = t & 1;
        uint32_t ab = sbase + (uint32_t)buf * TILEB;
        uint32_t bb = sbase + 2u * TILEB + (uint32_t)buf * TILEB;
        #pragma unroll
        for (int ks = 0; ks < 4; ks++) {
            int kb = ks * 16;
            uint32_t af[4][4], bf[4][2];
            #pragma unroll
            for (int mt = 0; mt < 4; mt++) {
                uint32_t a = ab + (uint32_t)(wm + mt*16 + (sel & 1)*8 + lr) * 144
                                + (uint32_t)(kb + (sel >> 1)*8) * 2;
                ldsm4(af[mt][0], af[mt][1], af[mt][2], af[mt][3], a);
            }
            #pragma unroll
            for (int q = 0; q < 2; q++) {
                uint32_t a = bb + (uint32_t)(wn + q*16 + (sel >> 1)*8 + lr) * 144
                                + (uint32_t)(kb + (sel & 1)*8) * 2;
                ldsm4(bf[q*2][0], bf[q*2][1], bf[q*2+1][0], bf[q*2+1][1], a);
            }
            #pragma unroll
            for (int mt = 0; mt < 4; mt++)
                #pragma unroll
                for (int nt = 0; nt < 4; nt++)
                    mma_f16(acc[mt][nt], af[mt][0], af[mt][1], af[mt][2], af[mt][3],
                            bf[nt][0], bf[nt][1]);
        }
        __syncthreads();
        if (t + 2 < ntls) { load_tile(t + 2, buf); CP_COMMIT(); }
    }

    #pragma unroll
    for (int mt = 0; mt < 4; mt++)
        #pragma unroll
        for (int nt = 0; nt < 4; nt++)
            #pragma unroll
            for (int h = 0; h < 2; h++) {
                size_t row = m0 + wm + mt*16 + g + h*8;
                int col = (int)n0 + wn + nt*8 + tg*2;
                float v0 = acc[mt][nt][h*2+0], v1 = acc[mt][nt][h*2+1];
                if (epi == 1) { v0 = fmaxf(v0, 0.f); v1 = fmaxf(v1, 0.f); }
                else if (epi == 2) { v0 = 1.f/(1.f+expf(-v0)); v1 = 1.f/(1.f+expf(-v1)); }
                *(__half2*)&D[row * (size_t)N + col] = __floats2half2_rn(v0, v1);
            }
}

// ===== conv1d(K=3) as GEMM with A-tile reuse across taps ====================
// A = activations [B,L,C] fp16; one 130-row halo tile per 64-ci chunk serves
// all 3 taps (A-frag row +p). B = weights [co][tap*C+ci]. 12 steps = 4 ci x 3 tap.
// epi: 3 BN, 4 BN+relu (column-wise affine e1/e2 over co).
#define CATILE (132*144)             // 19008 (130 rows used)
#define CBTILE (128*144)             // 18432
#define CONV_SMEM (2*CATILE + 2*CBTILE)   // 74880

__global__ void __launch_bounds__(256, 2)
convh(const __half* __restrict__ A, const __half* __restrict__ Bw,
      __half* __restrict__ D,
      const float* __restrict__ e1, const float* __restrict__ e2, int do_relu) {
    extern __shared__ unsigned char sm[];
    const uint32_t sbase = smem_u32(sm);

    int tid = threadIdx.x, lane = tid & 31, wid = tid >> 5;
    int wm = (wid & 1) * 64, wn = (wid >> 1) * 32;
    int g = lane >> 2, tg = lane & 3;
    int lr = lane & 7, sel = lane >> 3;
    size_t n0 = (size_t)blockIdx.x * 128;   // co
    size_t m0 = (size_t)blockIdx.y * 128;   // (b,l)
    int bidx = (int)(m0 >> 12);
    int l0   = (int)(m0 & (L_ - 1));

    float acc[4][4][4] = {};

    // A chunk c: rows l0-1 .. l0+128 (130), ci = c*64 .. +64
    auto loadA = [&](int c, int buf) {
        uint32_t ab = sbase + (uint32_t)buf * CATILE;
        #pragma unroll
        for (int i = 0; i < 5; i++) {
            int ch = tid + i * 256;
            if (ch < 130 * 8) {
                int r = ch >> 3, c16 = ch & 7;
                int l = l0 + r - 1;
                uint32_t sz = ((unsigned)l < (unsigned)L_) ? 16u : 0u;
                int lc = l < 0 ? 0 : (l >= L_ ? L_ - 1 : l);
                cp16p(ab + (uint32_t)(r * 144 + c16 * 16),
                      &A[((size_t)bidx * L_ + lc) * C_ + c * 64 + c16 * 8], sz);
            }
        }
    };
    // B step (c,p): weights cols p*C + c*64 .. +64
    auto loadB = [&](int c, int p, int buf) {
        uint32_t bb = sbase + 2u * CATILE + (uint32_t)buf * CBTILE;
        #pragma unroll
        for (int i = 0; i < 4; i++) {
            int ch = tid + i * 256;
            int r = ch >> 3, c16 = ch & 7;
            cp16p(bb + (uint32_t)(r * 144 + c16 * 16),
                  &Bw[(n0 + r) * (size_t)(3*C_) + p * C_ + c * 64 + c16 * 8], 16);
        }
    };

    // prologue: group(step0) = A0+B(0,0); group(step1) = B(0,1)
    loadA(0, 0); loadB(0, 0, 0); CP_COMMIT();
    loadB(0, 1, 1); CP_COMMIT();

    int c = 0, p = 0;
    for (int s = 0; s < 12; s++) {
        if (s + 1 < 12) CP_WAIT1(); else CP_WAIT0();
        __syncthreads();                         // step s resident
        uint32_t ab = sbase + (uint32_t)(c & 1) * CATILE;
        uint32_t bb = sbase + 2u * CATILE + (uint32_t)(s & 1) * CBTILE;
        #pragma unroll
        for (int ks = 0; ks < 4; ks++) {
            int kb = ks * 16;
            uint32_t af[4][4], bf[4][2];
            #pragma unroll
            for (int mt = 0; mt < 4; mt++) {
                uint32_t a = ab + (uint32_t)(wm + mt*16 + (sel & 1)*8 + lr + p) * 144
                                + (uint32_t)(kb + (sel >> 1)*8) * 2;
                ldsm4(af[mt][0], af[mt][1], af[mt][2], af[mt][3], a);
            }
            #pragma unroll
            for (int q = 0; q < 2; q++) {
                uint32_t a = bb + (uint32_t)(wn + q*16 + (sel >> 1)*8 + lr) * 144
                                + (uint32_t)(kb + (sel & 1)*8) * 2;
                ldsm4(bf[q*2][0], bf[q*2][1], bf[q*2+1][0], bf[q*2+1][1], a);
            }
            #pragma unroll
            for (int mt = 0; mt < 4; mt++)
                #pragma unroll
                for (int nt = 0; nt < 4; nt++)
                    mma_f16(acc[mt][nt], af[mt][0], af[mt][1], af[mt][2], af[mt][3],
                            bf[nt][0], bf[nt][1]);
        }
        __syncthreads();                         // slot (s&1) / A-buf free
        if (s + 2 < 12) {
            // step s+2: tap p2, chunk c2
            int p2 = (p >= 1) ? p - 1 : 2;
            int c2 = (p >= 1) ? c + 1 : c;
            if (p == 1) loadA(c + 1, (c + 1) & 1);   // first use at step 3(c+1)
            loadB(c2, p2, s & 1);
            CP_COMMIT();
        }
        p++; if (p == 3) { p = 0; c++; }
    }

    // ---- BN (+relu) epilogue, D = [B,L,C] ----------------------------------
    #pragma unroll
    for (int mt = 0; mt < 4; mt++)
        #pragma unroll
        for (int nt = 0; nt < 4; nt++)
            #pragma unroll
            for (int h = 0; h < 2; h++) {
                size_t row = m0 + wm + mt*16 + g + h*8;
                int col = (int)n0 + wn + nt*8 + tg*2;
                float v0 = acc[mt][nt][h*2+0] * e1[col]   + e2[col];
                float v1 = acc[mt][nt][h*2+1] * e1[col+1] + e2[col+1];
                if (do_relu) { v0 = fmaxf(v0, 0.f); v1 = fmaxf(v1, 0.f); }
                *(__half2*)&D[row * (size_t)C_ + col] = __floats2half2_rn(v0, v1);
            }
}

// ---------------- LayerNorm (fp16 data): warp per row, in-place ------------
__global__ void ln_kernel(__half* __restrict__ data,
                          const float* __restrict__ gw, const float* __restrict__ bw) {
    int lane = threadIdx.x & 31, warp = threadIdx.x >> 5;
    size_t row = (size_t)blockIdx.x * 8 + warp;
    uint4* p = (uint4*)(data + row * C_);
    uint4 raw = p[lane];
    __half2 hp[4];
    *(uint4*)hp = raw;
    float v[8];
    #pragma unroll
    for (int q = 0; q < 4; q++) {
        float2 f = __half22float2(hp[q]);
        v[q*2] = f.x; v[q*2+1] = f.y;
    }
    float s = 0.f;
    #pragma unroll
    for (int j = 0; j < 8; j++) s += v[j];
    #pragma unroll
    for (int o = 16; o; o >>= 1) s += __shfl_xor_sync(0xffffffffu, s, o);
    float mean = s * (1.f / C_);
    float s2 = 0.f;
    #pragma unroll
    for (int j = 0; j < 8; j++) { v[j] -= mean; s2 += v[j]*v[j]; }
    #pragma unroll
    for (int o = 16; o; o >>= 1) s2 += __shfl_xor_sync(0xffffffffu, s2, o);
    float inv = rsqrtf(s2 * (1.f / C_) + 1e-6f);

    const float4* g4 = (const float4*)gw;
    const float4* b4 = (const float4*)bw;
    float4 ga = g4[lane*2], gb = g4[lane*2+1], ba = b4[lane*2], bb = b4[lane*2+1];
    float gv[8] = {ga.x, ga.y, ga.z, ga.w, gb.x, gb.y, gb.z, gb.w};
    float bv[8] = {ba.x, ba.y, ba.z, ba.w, bb.x, bb.y, bb.z, bb.w};
    #pragma unroll
    for (int q = 0; q < 4; q++)
        hp[q] = __floats2half2_rn(v[q*2]*inv*gv[q*2] + bv[q*2],
                                  v[q*2+1]*inv*gv[q*2+1] + bv[q*2+1]);
    p[lane] = *(uint4*)hp;
}

// ==== fused LN2 + final (R10): out = relu(xp[b,l,c]*LN(fw)[b,l,c] + x) =====
__global__ void ln_final_kernel(const __half* __restrict__ t1, const __half* __restrict__ xp,
                                const float* __restrict__ x,
                                const float* __restrict__ gw, const float* __restrict__ bw,
                                float* __restrict__ out) {
    __shared__ float tile[32][257];
    int tid = threadIdx.x, lane = tid & 31, warp = tid >> 5;
    int b = blockIdx.y, l0 = blockIdx.x * 32;

    const float4* g4 = (const float4*)gw;
    const float4* b4 = (const float4*)bw;
    float4 ga = g4[lane*2], gb = g4[lane*2+1], ba = b4[lane*2], bb = b4[lane*2+1];
    float gv[8] = {ga.x, ga.y, ga.z, ga.w, gb.x, gb.y, gb.z, gb.w};
    float bv[8] = {ba.x, ba.y, ba.z, ba.w, bb.x, bb.y, bb.z, bb.w};

    #pragma unroll
    for (int r = 0; r < 4; r++) {
        int rt = r * 8 + warp;
        size_t row = (size_t)b * L_ + l0 + rt;
        uint4 raw = ((const uint4*)(t1 + row * C_))[lane];
        __half2 hp[4]; *(uint4*)hp = raw;
        float v[8];
        #pragma unroll
        for (int q = 0; q < 4; q++) {
            float2 f = __half22float2(hp[q]);
            v[q*2] = f.x; v[q*2+1] = f.y;
        }
        float s = 0.f;
        #pragma unroll
        for (int j = 0; j < 8; j++) s += v[j];
        #pragma unroll
        for (int o = 16; o; o >>= 1) s += __shfl_xor_sync(0xffffffffu, s, o);
        float mean = s * (1.f / C_);
        float s2 = 0.f;
        #pragma unroll
        for (int j = 0; j < 8; j++) { v[j] -= mean; s2 += v[j]*v[j]; }
        #pragma unroll
        for (int o = 16; o; o >>= 1) s2 += __shfl_xor_sync(0xffffffffu, s2, o);
        float inv = rsqrtf(s2 * (1.f / C_) + 1e-6f);

        uint4 xraw = ((const uint4*)(xp + row * C_))[lane];
        __half2 xh[4]; *(uint4*)xh = xraw;
        #pragma unroll
        for (int q = 0; q < 4; q++) {
            float2 xf = __half22float2(xh[q]);
            float fw0 = v[q*2]   * inv * gv[q*2]   + bv[q*2];
            float fw1 = v[q*2+1] * inv * gv[q*2+1] + bv[q*2+1];
            tile[rt][lane*8 + q*2]     = xf.x * fw0;
            tile[rt][lane*8 + q*2 + 1] = xf.y * fw1;
        }
    }
    __syncthreads();

    int lidx = tid & 31;
    int cg = tid >> 5;
    #pragma unroll
    for (int j = 0; j < 32; j++) {
        int ccol = cg * 32 + j;
        size_t gi = ((size_t)b * C_ + ccol) * L_ + l0 + lidx;
        out[gi] = fmaxf(tile[lidx][ccol] + x[gi], 0.f);
    }
}

// ---------------------------------------------------------------------------
extern "C" void kernel_launch(void* const* d_in, const int* in_sizes, int n_in,
                              void* d_out, int out_size) {
    const float* x       = (const float*)d_in[0];
    const float* conv1_w = (const float*)d_in[1];
    const float* bn1_g   = (const float*)d_in[2];
    const float* bn1_b   = (const float*)d_in[3];
    const float* bn1_m   = (const float*)d_in[4];
    const float* bn1_v   = (const float*)d_in[5];
    const float* conv2_w = (const float*)d_in[6];
    const float* bn2_g   = (const float*)d_in[7];
    const float* bn2_b   = (const float*)d_in[8];
    const float* bn2_m   = (const float*)d_in[9];
    const float* bn2_v   = (const float*)d_in[10];
    const float* fc1_w   = (const float*)d_in[11];
    const float* fc2_w   = (const float*)d_in[12];
    const float* ln_g    = (const float*)d_in[13];
    const float* ln_b    = (const float*)d_in[14];
    float* out = (float*)d_out;

    void *xt, *y1, *xp, *t1, *h, *dct, *fc1r, *fc2r, *w1r, *w2r;
    void *bn1s, *bn1t, *bn2s, *bn2t;
    cudaGetSymbolAddress(&xt,   g_xt);
    cudaGetSymbolAddress(&y1,   g_y1);
    cudaGetSymbolAddress(&xp,   g_xp);
    cudaGetSymbolAddress(&t1,   g_t1);
    cudaGetSymbolAddress(&h,    g_h);
    cudaGetSymbolAddress(&dct,  g_dct);
    cudaGetSymbolAddress(&fc1r, g_fc1r);
    cudaGetSymbolAddress(&fc2r, g_fc2r);
    cudaGetSymbolAddress(&w1r,  g_w1r);
    cudaGetSymbolAddress(&w2r,  g_w2r);
    cudaGetSymbolAddress(&bn1s, g_bn1s);
    cudaGetSymbolAddress(&bn1t, g_bn1t);
    cudaGetSymbolAddress(&bn2s, g_bn2s);
    cudaGetSymbolAddress(&bn2t, g_bn2t);

    cudaFuncSetAttribute(gemmh, cudaFuncAttributeMaxDynamicSharedMemorySize, GH_SMEM);
    cudaFuncSetAttribute(convh, cudaFuncAttributeMaxDynamicSharedMemorySize, CONV_SMEM);

    // 0. precompute fp16 weights + transpose/round x
    precompute_kernel<<<(3*C_*C_ + 255)/256, 256>>>(
        fc1_w, fc2_w, conv1_w, conv2_w,
        bn1_g, bn1_b, bn1_m, bn1_v, bn2_g, bn2_b, bn2_m, bn2_v);
    {
        dim3 grid(C_/32, L_/32, B_);
        transpose_round_kernel<<<grid, dim3(32, 8)>>>(x, (__half*)xt);
    }

    // 1. conv1+bn1+relu -> y1 [B,L,C]
    convh<<<dim3(C_/128, BL_/128), 256, CONV_SMEM>>>(
        (const __half*)xt, (const __half*)w1r, (__half*)y1,
        (const float*)bn1s, (const float*)bn1t, 1);
    // 2. conv2+bn2 -> xp [B,L,C]
    convh<<<dim3(C_/128, BL_/128), 256, CONV_SMEM>>>(
        (const __half*)y1, (const __half*)w2r, (__half*)xp,
        (const float*)bn2s, (const float*)bn2t, 0);
    // 3. freq = xp @ Dm^T -> t1
    gemmh<<<dim3(C_/128, BL_/128), 256, GH_SMEM>>>(
        (const __half*)xp, (const __half*)dct, (__half*)t1, C_, C_, 0);
    // 4. sd = LN(freq)
    ln_kernel<<<BL_/8, 256>>>((__half*)t1, ln_g, ln_b);
    // 5. h = relu(sd @ fc1^T)
    gemmh<<<dim3(H_/128, BL_/128), 256, GH_SMEM>>>(
        (const __half*)t1, (const __half*)fc1r, (__half*)h, H_, C_, 1);
    // 6. fw = sigmoid(h @ fc2^T) -> t1
    gemmh<<<dim3(C_/128, BL_/128), 256, GH_SMEM>>>(
        (const __half*)h, (const __half*)fc2r, (__half*)t1, C_, H_, 2);
    // 7+8. fused: fw = LN(t1); out = relu(transpose(xp*fw) + x)
    {
        dim3 grid(L_/32, B_);
        ln_final_kernel<<<grid, 256>>>((const __half*)t1, (const __half*)xp, x,
                                       ln_g, ln_b, out);
    }
}